// round 3
// baseline (speedup 1.0000x reference)
#include <cuda_runtime.h>
#include <cuda_fp16.h>
#include <cstdint>
#include <cstddef>

#define T_STEPS 512
#define DH      2048
#define DI      64
#define DO      64
#define BATCH   128
#define HC      64
#define NCHUNK  (DH / HC)        // 32
#define USTR2   136              // u32 stride for half2 k-pair arrays (conflict-free)

// ---- device scratch ----
__device__ float    g_sr0[DH * BATCH];
__device__ float    g_base[DH * BATCH];
__device__ unsigned g_win_h[NCHUNK * 2048];   // fp16x2 A-fragments, hi
__device__ unsigned g_win_l[NCHUNK * 2048];   // lo
__device__ unsigned g_wout_h[NCHUNK * 2048];
__device__ unsigned g_wout_l[NCHUNK * 2048];

// ---------- helpers ----------
union F2U { unsigned long long u; float2 f; };

__device__ __forceinline__ unsigned long long pack2(float w) {
    unsigned int wi = __float_as_uint(w);
    unsigned long long r;
    asm("mov.b64 %0, {%1, %1};" : "=l"(r) : "r"(wi));
    return r;
}
__device__ __forceinline__ void fma2(unsigned long long& d,
                                     unsigned long long a,
                                     unsigned long long b) {
    asm("fma.rn.f32x2 %0, %1, %2, %0;" : "+l"(d) : "l"(a), "l"(b));
}
__device__ __forceinline__ float sigm(float x) {
    return __fdividef(1.0f, 1.0f + __expf(-x));
}
// split x into fp16 hi + fp16 lo
__device__ __forceinline__ void sp16(float x, float& h, float& l) {
    h = __half2float(__float2half_rn(x));
    l = x - h;
}
__device__ __forceinline__ unsigned packh2(float a, float b) {
    __half2 h = __floats2half2_rn(a, b);   // a -> low half
    return *(unsigned*)&h;
}
__device__ __forceinline__ void mma_f16(float& c0, float& c1, float& c2, float& c3,
                                        unsigned a0, unsigned a1, unsigned a2, unsigned a3,
                                        unsigned b0, unsigned b1) {
    asm volatile("mma.sync.aligned.m16n8k16.row.col.f32.f16.f16.f32 "
                 "{%0,%1,%2,%3}, {%4,%5,%6,%7}, {%8,%9}, {%0,%1,%2,%3};"
                 : "+f"(c0), "+f"(c1), "+f"(c2), "+f"(c3)
                 : "r"(a0), "r"(a1), "r"(a2), "r"(a3), "r"(b0), "r"(b1));
}

// ---------- kernel 0: sigmoid(r0) ----------
__global__ void sig_kernel(const float* __restrict__ r0) {
    int i = (blockIdx.x * blockDim.x + threadIdx.x) * 4;
    float4 v = *(const float4*)(r0 + i);
    v.x = sigm(v.x); v.y = sigm(v.y); v.z = sigm(v.z); v.w = sigm(v.w);
    *(float4*)(g_sr0 + i) = v;
}

// ---------- kernel 1: base = (1-a)*r0 + a*(|W| @ sr0)  (validated R1) ----------
__global__ void __launch_bounds__(256, 2)
base_kernel(const float* __restrict__ r0,
            const float* __restrict__ w_,
            const float* __restrict__ taus) {
    extern __shared__ float sm[];
    float* sr_s = sm;
    float* w_s  = sm + 128 * 128;

    int tid = threadIdx.x;
    int cp  = tid & 31;
    int rg  = tid >> 5;
    int hbase = blockIdx.x * 16;

    unsigned long long acc[2][2] = {{0ull, 0ull}, {0ull, 0ull}};

    for (int kc = 0; kc < DH / 128; ++kc) {
        int k0 = kc * 128;
        __syncthreads();
        {
            const float4* src = (const float4*)(g_sr0 + (size_t)k0 * BATCH);
            float4* dst = (float4*)sr_s;
#pragma unroll
            for (int i = 0; i < 16; ++i) dst[tid + i * 256] = src[tid + i * 256];
        }
#pragma unroll
        for (int j = 0; j < 2; ++j) {
            int e  = j * 1024 + tid * 4;
            int r  = e >> 7;
            int kk = e & 127;
            float4 wv = *(const float4*)(w_ + (size_t)(hbase + r) * DH + k0 + kk);
            wv.x = fabsf(wv.x); wv.y = fabsf(wv.y);
            wv.z = fabsf(wv.z); wv.w = fabsf(wv.w);
            *(float4*)(w_s + r * 128 + kk) = wv;
        }
        __syncthreads();

#pragma unroll 4
        for (int kk = 0; kk < 128; ++kk) {
            ulonglong2 sv = *(const ulonglong2*)(sr_s + kk * BATCH + 4 * cp);
#pragma unroll
            for (int r = 0; r < 2; ++r) {
                unsigned long long pw = pack2(w_s[(rg * 2 + r) * 128 + kk]);
                fma2(acc[r][0], pw, sv.x);
                fma2(acc[r][1], pw, sv.y);
            }
        }
    }

#pragma unroll
    for (int r = 0; r < 2; ++r) {
        int h = hbase + rg * 2 + r;
        float alpha = 1.0f / taus[h];
        float om = 1.0f - alpha;
        float4 rv = *(const float4*)(r0 + (size_t)h * BATCH + 4 * cp);
        F2U lo, hi; lo.u = acc[r][0]; hi.u = acc[r][1];
        float4 o;
        o.x = om * rv.x + alpha * lo.f.x;
        o.y = om * rv.y + alpha * lo.f.y;
        o.z = om * rv.z + alpha * hi.f.x;
        o.w = om * rv.w + alpha * hi.f.y;
        *(float4*)(g_base + (size_t)h * BATCH + 4 * cp) = o;
    }
}

// ---------- kernel 2: pack win into fp16 hi/lo A-fragments (m16n8k16) ----------
// tg = (c, kt, mt, lane): 32 chunks x 4 kt x 4 mt x 32 lanes = 16384 threads
__global__ void pack_win_kernel(const float* __restrict__ win) {
    int tg = blockIdx.x * blockDim.x + threadIdx.x;
    int lane = tg & 31;
    int mt = (tg >> 5) & 3;
    int kt = (tg >> 7) & 3;
    int c  = tg >> 9;
    int r0 = (c * 4 + mt) * 16 + (lane >> 2);
    int k0 = kt * 16 + 2 * (lane & 3);

    float v[8] = { win[r0 * DI + k0],           win[r0 * DI + k0 + 1],
                   win[(r0 + 8) * DI + k0],     win[(r0 + 8) * DI + k0 + 1],
                   win[r0 * DI + k0 + 8],       win[r0 * DI + k0 + 9],
                   win[(r0 + 8) * DI + k0 + 8], win[(r0 + 8) * DI + k0 + 9] };
    float h[8], l[8];
#pragma unroll
    for (int i = 0; i < 8; ++i) sp16(v[i], h[i], l[i]);
    uint4 oh = { packh2(h[0], h[1]), packh2(h[2], h[3]),
                 packh2(h[4], h[5]), packh2(h[6], h[7]) };
    uint4 ol = { packh2(l[0], l[1]), packh2(l[2], l[3]),
                 packh2(l[4], l[5]), packh2(l[6], l[7]) };
    *(uint4*)(g_win_h + (size_t)tg * 4) = oh;
    *(uint4*)(g_win_l + (size_t)tg * 4) = ol;
}

// ---------- kernel 3: pack wout into fp16 hi/lo A-fragments ----------
__global__ void pack_wout_kernel(const float* __restrict__ wout) {
    int tg = blockIdx.x * blockDim.x + threadIdx.x;
    int lane = tg & 31;
    int mt = (tg >> 5) & 3;
    int kt = (tg >> 7) & 3;
    int c  = tg >> 9;
    int r0 = mt * 16 + (lane >> 2);
    int k0 = c * HC + kt * 16 + 2 * (lane & 3);

    float v[8] = { wout[r0 * DH + k0],           wout[r0 * DH + k0 + 1],
                   wout[(r0 + 8) * DH + k0],     wout[(r0 + 8) * DH + k0 + 1],
                   wout[r0 * DH + k0 + 8],       wout[r0 * DH + k0 + 9],
                   wout[(r0 + 8) * DH + k0 + 8], wout[(r0 + 8) * DH + k0 + 9] };
    float h[8], l[8];
#pragma unroll
    for (int i = 0; i < 8; ++i) sp16(v[i], h[i], l[i]);
    uint4 oh = { packh2(h[0], h[1]), packh2(h[2], h[3]),
                 packh2(h[4], h[5]), packh2(h[6], h[7]) };
    uint4 ol = { packh2(l[0], l[1]), packh2(l[2], l[3]),
                 packh2(l[4], l[5]), packh2(l[6], l[7]) };
    *(uint4*)(g_wout_h + (size_t)tg * 4) = oh;
    *(uint4*)(g_wout_l + (size_t)tg * 4) = ol;
}

// ---------- main kernel ----------
// smem (u32 units):
//  u_hi [0,4352)  u_lo [4352,8704)
//  A1h  [8704,10752)  A1l [10752,12800)
//  W2h  [12800,14848) W2l [14848,16896)
//  S_h  [16896,21248) S_l [21248,25600)
#define OFF_ULO 4352
#define OFF_A1H 8704
#define OFF_A1L 10752
#define OFF_W2H 12800
#define OFF_W2L 14848
#define OFF_SH  16896
#define OFF_SL  21248
#define SMEM_U32 25600

__global__ void __launch_bounds__(256, 1)
main_kernel(const float* __restrict__ u,
            const float* __restrict__ noise,
            const float* __restrict__ bias,
            float* __restrict__ out) {
    extern __shared__ unsigned smu[];
    unsigned* u_hi = smu;
    unsigned* u_lo = smu + OFF_ULO;
    unsigned* A1h  = smu + OFF_A1H;
    unsigned* A1l  = smu + OFF_A1L;
    unsigned* W2h  = smu + OFF_W2H;
    unsigned* W2l  = smu + OFF_W2L;
    unsigned* S_h  = smu + OFF_SH;
    unsigned* S_l  = smu + OFF_SL;
    __half* SHh = (__half*)S_h;
    __half* SLh = (__half*)S_l;

    int tid  = threadIdx.x;
    int lane = tid & 31;
    int w    = tid >> 5;
    int qq   = lane & 3;
    int rr   = lane >> 2;

    float* xsout = out + (size_t)T_STEPS * DO * BATCH;

    for (int tt = 0; tt < 4; ++tt) {
        int t = blockIdx.x * 4 + tt;

        // ---- stage u[t]: split into fp16 hi/lo, k-pair interleaved ----
        {
            const float* ut = u + (size_t)t * DI * BATCH;
#pragma unroll
            for (int i = 0; i < 8; ++i) {
                int idx = tid + i * 256;        // 0..2047
                int dp  = idx >> 6;             // 0..31 (d pair)
                int b2  = (idx & 63) * 2;       // 0..126
                float2 ra = *(const float2*)(ut + (2 * dp) * BATCH + b2);
                float2 rb = *(const float2*)(ut + (2 * dp + 1) * BATCH + b2);
                float h00, l00, h10, l10, h01, l01, h11, l11;
                sp16(ra.x, h00, l00); sp16(rb.x, h10, l10);
                sp16(ra.y, h01, l01); sp16(rb.y, h11, l11);
                uint2 hw = { packh2(h00, h10), packh2(h01, h11) };
                uint2 lw = { packh2(l00, l10), packh2(l01, l11) };
                *(uint2*)(u_hi + dp * USTR2 + b2) = hw;
                *(uint2*)(u_lo + dp * USTR2 + b2) = lw;
            }
        }

        float C2[4][2][4];
#pragma unroll
        for (int a = 0; a < 4; ++a)
#pragma unroll
            for (int b = 0; b < 2; ++b)
#pragma unroll
                for (int q = 0; q < 4; ++q) C2[a][b][q] = 0.0f;

        for (int c = 0; c < NCHUNK; ++c) {
            __syncthreads();   // prior chunk's W2/S consumers done; u staged (c==0)

            // ---- stage weight fragments ----
            {
                const uint4* gwh = ((const uint4*)g_win_h)  + (size_t)c * 512;
                const uint4* gwl = ((const uint4*)g_win_l)  + (size_t)c * 512;
                const uint4* goh = ((const uint4*)g_wout_h) + (size_t)c * 512;
                const uint4* gol = ((const uint4*)g_wout_l) + (size_t)c * 512;
#pragma unroll
                for (int i = 0; i < 2; ++i) {
                    ((uint4*)A1h)[tid + i * 256] = gwh[tid + i * 256];
                    ((uint4*)A1l)[tid + i * 256] = gwl[tid + i * 256];
                    ((uint4*)W2h)[tid + i * 256] = goh[tid + i * 256];
                    ((uint4*)W2l)[tid + i * 256] = gol[tid + i * 256];
                }
            }
            __syncthreads();

            // ---- GEMM1: inp = win_chunk @ u[t], fp16 3-pass ----
            float C1[4][2][4];
#pragma unroll
            for (int a = 0; a < 4; ++a)
#pragma unroll
                for (int b = 0; b < 2; ++b)
#pragma unroll
                    for (int q = 0; q < 4; ++q) C1[a][b][q] = 0.0f;

#pragma unroll
            for (int kt = 0; kt < 4; ++kt) {
                unsigned bh0[2], bh1[2], bl0[2], bl1[2];
#pragma unroll
                for (int nt = 0; nt < 2; ++nt) {
                    int n = w * 16 + nt * 8 + rr;
                    bh0[nt] = u_hi[(kt * 8 + qq) * USTR2 + n];
                    bh1[nt] = u_hi[(kt * 8 + 4 + qq) * USTR2 + n];
                    bl0[nt] = u_lo[(kt * 8 + qq) * USTR2 + n];
                    bl1[nt] = u_lo[(kt * 8 + 4 + qq) * USTR2 + n];
                }
#pragma unroll
                for (int mt = 0; mt < 4; ++mt) {
                    uint4 ah = *(const uint4*)(A1h + ((kt * 4 + mt) * 32 + lane) * 4);
                    uint4 al = *(const uint4*)(A1l + ((kt * 4 + mt) * 32 + lane) * 4);
#pragma unroll
                    for (int nt = 0; nt < 2; ++nt) {
                        mma_f16(C1[mt][nt][0], C1[mt][nt][1], C1[mt][nt][2], C1[mt][nt][3],
                                ah.x, ah.y, ah.z, ah.w, bh0[nt], bh1[nt]);
                        mma_f16(C1[mt][nt][0], C1[mt][nt][1], C1[mt][nt][2], C1[mt][nt][3],
                                ah.x, ah.y, ah.z, ah.w, bl0[nt], bl1[nt]);
                        mma_f16(C1[mt][nt][0], C1[mt][nt][1], C1[mt][nt][2], C1[mt][nt][3],
                                al.x, al.y, al.z, al.w, bh0[nt], bh1[nt]);
                    }
                }
            }

            // ---- epilogue: xs = inp + base + noise; write xs; S = fp16 hi/lo(sigm) ----
#pragma unroll
            for (int mt = 0; mt < 4; ++mt) {
#pragma unroll
                for (int nt = 0; nt < 2; ++nt) {
                    int n0 = w * 16 + nt * 8 + 2 * qq;
#pragma unroll
                    for (int hh = 0; hh < 2; ++hh) {
                        int rl = mt * 16 + rr + hh * 8;
                        int hg = c * HC + rl;
                        size_t gi = ((size_t)t * DH + hg) * BATCH + n0;
                        float2 nz = *(const float2*)(noise + gi);
                        float2 bs = *(const float2*)(g_base + (size_t)hg * BATCH + n0);
                        float x0 = C1[mt][nt][hh * 2]     + nz.x + bs.x;
                        float x1 = C1[mt][nt][hh * 2 + 1] + nz.y + bs.y;
                        *(float2*)(xsout + gi) = make_float2(x0, x1);
                        float s0 = sigm(x0), s1 = sigm(x1);
                        float s0h, s0l, s1h, s1l;
                        sp16(s0, s0h, s0l); sp16(s1, s1h, s1l);
                        int hp = rl >> 1, par = rl & 1;
                        int w0 = hp * USTR2 + n0;
                        SHh[w0 * 2 + par]       = __float2half_rn(s0h);
                        SHh[(w0 + 1) * 2 + par] = __float2half_rn(s1h);
                        SLh[w0 * 2 + par]       = __float2half_rn(s0l);
                        SLh[(w0 + 1) * 2 + par] = __float2half_rn(s1l);
                    }
                }
            }
            __syncthreads();   // S ready

            // ---- GEMM2: out += wout_chunk @ s, fp16 3-pass ----
#pragma unroll
            for (int kt = 0; kt < 4; ++kt) {
                unsigned sh0[2], sh1[2], sl0[2], sl1[2];
#pragma unroll
                for (int nt = 0; nt < 2; ++nt) {
                    int n = w * 16 + nt * 8 + rr;
                    sh0[nt] = S_h[(kt * 8 + qq) * USTR2 + n];
                    sh1[nt] = S_h[(kt * 8 + 4 + qq) * USTR2 + n];
                    sl0[nt] = S_l[(kt * 8 + qq) * USTR2 + n];
                    sl1[nt] = S_l[(kt * 8 + 4 + qq) * USTR2 + n];
                }
#pragma unroll
                for (int mt = 0; mt < 4; ++mt) {
                    uint4 ah = *(const uint4*)(W2h + ((kt * 4 + mt) * 32 + lane) * 4);
                    uint4 al = *(const uint4*)(W2l + ((kt * 4 + mt) * 32 + lane) * 4);
#pragma unroll
                    for (int nt = 0; nt < 2; ++nt) {
                        mma_f16(C2[mt][nt][0], C2[mt][nt][1], C2[mt][nt][2], C2[mt][nt][3],
                                ah.x, ah.y, ah.z, ah.w, sh0[nt], sh1[nt]);
                        mma_f16(C2[mt][nt][0], C2[mt][nt][1], C2[mt][nt][2], C2[mt][nt][3],
                                ah.x, ah.y, ah.z, ah.w, sl0[nt], sl1[nt]);
                        mma_f16(C2[mt][nt][0], C2[mt][nt][1], C2[mt][nt][2], C2[mt][nt][3],
                                al.x, al.y, al.z, al.w, sh0[nt], sh1[nt]);
                    }
                }
            }
        }

        // ---- write outputs[t] ----
#pragma unroll
        for (int mt = 0; mt < 4; ++mt) {
#pragma unroll
            for (int nt = 0; nt < 2; ++nt) {
                int o0 = mt * 16 + rr;
                int n0 = w * 16 + nt * 8 + 2 * qq;
                float bv0 = __ldg(bias + o0);
                float bv8 = __ldg(bias + o0 + 8);
                *(float2*)(out + ((size_t)t * DO + o0) * BATCH + n0) =
                    make_float2(C2[mt][nt][0] + bv0, C2[mt][nt][1] + bv0);
                *(float2*)(out + ((size_t)t * DO + o0 + 8) * BATCH + n0) =
                    make_float2(C2[mt][nt][2] + bv8, C2[mt][nt][3] + bv8);
            }
        }
        __syncthreads();   // protect u/S overwrite next tt
    }
}

extern "C" void kernel_launch(void* const* d_in, const int* in_sizes, int n_in,
                              void* d_out, int out_size) {
    const float* u     = (const float*)d_in[0];
    const float* r0    = (const float*)d_in[1];
    const float* noise = (const float*)d_in[2];
    const float* win   = (const float*)d_in[3];
    const float* w_    = (const float*)d_in[4];
    // d_in[5] = m_diag: unused — |_w * (+-1)| == |_w|
    const float* wout  = (const float*)d_in[6];
    const float* bias  = (const float*)d_in[7];
    const float* taus  = (const float*)d_in[8];
    float* out = (float*)d_out;

    const int base_smem = (128 * 128 + 16 * 128) * 4;
    const int main_smem = SMEM_U32 * 4;   // 102400 B
    cudaFuncSetAttribute(base_kernel, cudaFuncAttributeMaxDynamicSharedMemorySize, base_smem);
    cudaFuncSetAttribute(main_kernel, cudaFuncAttributeMaxDynamicSharedMemorySize, main_smem);

    sig_kernel<<<256, 256>>>(r0);
    base_kernel<<<DH / 16, 256, base_smem>>>(r0, w_, taus);
    pack_win_kernel<<<64, 256>>>(win);
    pack_wout_kernel<<<64, 256>>>(wout);
    main_kernel<<<128, 256, main_smem>>>(u, noise, bias, out);
}

// round 4
// speedup vs baseline: 1.2160x; 1.2160x over previous
#include <cuda_runtime.h>
#include <cuda_fp16.h>
#include <cstdint>
#include <cstddef>

#define T_STEPS 512
#define DH      2048
#define DI      64
#define DO      64
#define BATCH   128
#define HC      64
#define NCHUNK  (DH / HC)        // 32
#define NB      64               // batch cols per block
#define USTR    72               // u32 stride for 64-wide half2 k-pair arrays

// ---- device scratch ----
__device__ float    g_sr0[DH * BATCH];
__device__ float    g_base[DH * BATCH];
__device__ unsigned g_win_h[NCHUNK * 2048];   // fp16x2 A-fragments, hi
__device__ unsigned g_win_l[NCHUNK * 2048];
__device__ unsigned g_wout_h[NCHUNK * 2048];
__device__ unsigned g_wout_l[NCHUNK * 2048];

// ---------- helpers ----------
union F2U { unsigned long long u; float2 f; };

__device__ __forceinline__ unsigned long long pack2(float w) {
    unsigned int wi = __float_as_uint(w);
    unsigned long long r;
    asm("mov.b64 %0, {%1, %1};" : "=l"(r) : "r"(wi));
    return r;
}
__device__ __forceinline__ void fma2(unsigned long long& d,
                                     unsigned long long a,
                                     unsigned long long b) {
    asm("fma.rn.f32x2 %0, %1, %2, %0;" : "+l"(d) : "l"(a), "l"(b));
}
__device__ __forceinline__ float sigm(float x) {
    return __fdividef(1.0f, 1.0f + __expf(-x));
}
__device__ __forceinline__ void sp16(float x, float& h, float& l) {
    h = __half2float(__float2half_rn(x));
    l = x - h;
}
__device__ __forceinline__ unsigned packh2(float a, float b) {
    __half2 h = __floats2half2_rn(a, b);
    return *(unsigned*)&h;
}
__device__ __forceinline__ void mma_f16(float& c0, float& c1, float& c2, float& c3,
                                        unsigned a0, unsigned a1, unsigned a2, unsigned a3,
                                        unsigned b0, unsigned b1) {
    asm volatile("mma.sync.aligned.m16n8k16.row.col.f32.f16.f16.f32 "
                 "{%0,%1,%2,%3}, {%4,%5,%6,%7}, {%8,%9}, {%0,%1,%2,%3};"
                 : "+f"(c0), "+f"(c1), "+f"(c2), "+f"(c3)
                 : "r"(a0), "r"(a1), "r"(a2), "r"(a3), "r"(b0), "r"(b1));
}

// ---------- kernel 0: sigmoid(r0) ----------
__global__ void sig_kernel(const float* __restrict__ r0) {
    int i = (blockIdx.x * blockDim.x + threadIdx.x) * 4;
    float4 v = *(const float4*)(r0 + i);
    v.x = sigm(v.x); v.y = sigm(v.y); v.z = sigm(v.z); v.w = sigm(v.w);
    *(float4*)(g_sr0 + i) = v;
}

// ---------- kernel 1: base = (1-a)*r0 + a*(|W| @ sr0) ----------
__global__ void __launch_bounds__(256, 2)
base_kernel(const float* __restrict__ r0,
            const float* __restrict__ w_,
            const float* __restrict__ taus) {
    extern __shared__ float sm[];
    float* sr_s = sm;
    float* w_s  = sm + 128 * 128;

    int tid = threadIdx.x;
    int cp  = tid & 31;
    int rg  = tid >> 5;
    int hbase = blockIdx.x * 16;

    unsigned long long acc[2][2] = {{0ull, 0ull}, {0ull, 0ull}};

    for (int kc = 0; kc < DH / 128; ++kc) {
        int k0 = kc * 128;
        __syncthreads();
        {
            const float4* src = (const float4*)(g_sr0 + (size_t)k0 * BATCH);
            float4* dst = (float4*)sr_s;
#pragma unroll
            for (int i = 0; i < 16; ++i) dst[tid + i * 256] = src[tid + i * 256];
        }
#pragma unroll
        for (int j = 0; j < 2; ++j) {
            int e  = j * 1024 + tid * 4;
            int r  = e >> 7;
            int kk = e & 127;
            float4 wv = *(const float4*)(w_ + (size_t)(hbase + r) * DH + k0 + kk);
            wv.x = fabsf(wv.x); wv.y = fabsf(wv.y);
            wv.z = fabsf(wv.z); wv.w = fabsf(wv.w);
            *(float4*)(w_s + r * 128 + kk) = wv;
        }
        __syncthreads();

#pragma unroll 4
        for (int kk = 0; kk < 128; ++kk) {
            ulonglong2 sv = *(const ulonglong2*)(sr_s + kk * BATCH + 4 * cp);
#pragma unroll
            for (int r = 0; r < 2; ++r) {
                unsigned long long pw = pack2(w_s[(rg * 2 + r) * 128 + kk]);
                fma2(acc[r][0], pw, sv.x);
                fma2(acc[r][1], pw, sv.y);
            }
        }
    }

#pragma unroll
    for (int r = 0; r < 2; ++r) {
        int h = hbase + rg * 2 + r;
        float alpha = 1.0f / taus[h];
        float om = 1.0f - alpha;
        float4 rv = *(const float4*)(r0 + (size_t)h * BATCH + 4 * cp);
        F2U lo, hi; lo.u = acc[r][0]; hi.u = acc[r][1];
        float4 o;
        o.x = om * rv.x + alpha * lo.f.x;
        o.y = om * rv.y + alpha * lo.f.y;
        o.z = om * rv.z + alpha * hi.f.x;
        o.w = om * rv.w + alpha * hi.f.y;
        *(float4*)(g_base + (size_t)h * BATCH + 4 * cp) = o;
    }
}

// ---------- kernel 2: pack win into fp16 hi/lo A-fragments ----------
__global__ void pack_win_kernel(const float* __restrict__ win) {
    int tg = blockIdx.x * blockDim.x + threadIdx.x;   // 16384
    int lane = tg & 31;
    int mt = (tg >> 5) & 3;
    int kt = (tg >> 7) & 3;
    int c  = tg >> 9;
    int r0 = (c * 4 + mt) * 16 + (lane >> 2);
    int k0 = kt * 16 + 2 * (lane & 3);

    float v[8] = { win[r0 * DI + k0],           win[r0 * DI + k0 + 1],
                   win[(r0 + 8) * DI + k0],     win[(r0 + 8) * DI + k0 + 1],
                   win[r0 * DI + k0 + 8],       win[r0 * DI + k0 + 9],
                   win[(r0 + 8) * DI + k0 + 8], win[(r0 + 8) * DI + k0 + 9] };
    float h[8], l[8];
#pragma unroll
    for (int i = 0; i < 8; ++i) sp16(v[i], h[i], l[i]);
    uint4 oh = { packh2(h[0], h[1]), packh2(h[2], h[3]),
                 packh2(h[4], h[5]), packh2(h[6], h[7]) };
    uint4 ol = { packh2(l[0], l[1]), packh2(l[2], l[3]),
                 packh2(l[4], l[5]), packh2(l[6], l[7]) };
    *(uint4*)(g_win_h + (size_t)tg * 4) = oh;
    *(uint4*)(g_win_l + (size_t)tg * 4) = ol;
}

// ---------- kernel 3: pack wout into fp16 hi/lo A-fragments ----------
__global__ void pack_wout_kernel(const float* __restrict__ wout) {
    int tg = blockIdx.x * blockDim.x + threadIdx.x;   // 16384
    int lane = tg & 31;
    int mt = (tg >> 5) & 3;
    int kt = (tg >> 7) & 3;
    int c  = tg >> 9;
    int r0 = mt * 16 + (lane >> 2);
    int k0 = c * HC + kt * 16 + 2 * (lane & 3);

    float v[8] = { wout[r0 * DH + k0],           wout[r0 * DH + k0 + 1],
                   wout[(r0 + 8) * DH + k0],     wout[(r0 + 8) * DH + k0 + 1],
                   wout[r0 * DH + k0 + 8],       wout[r0 * DH + k0 + 9],
                   wout[(r0 + 8) * DH + k0 + 8], wout[(r0 + 8) * DH + k0 + 9] };
    float h[8], l[8];
#pragma unroll
    for (int i = 0; i < 8; ++i) sp16(v[i], h[i], l[i]);
    uint4 oh = { packh2(h[0], h[1]), packh2(h[2], h[3]),
                 packh2(h[4], h[5]), packh2(h[6], h[7]) };
    uint4 ol = { packh2(l[0], l[1]), packh2(l[2], l[3]),
                 packh2(l[4], l[5]), packh2(l[6], l[7]) };
    *(uint4*)(g_wout_h + (size_t)tg * 4) = oh;
    *(uint4*)(g_wout_l + (size_t)tg * 4) = ol;
}

// ---------- main kernel ----------
// grid 1024: block = (t, batch-half). 8 warps; warp w owns n-slice of 8 cols.
// smem (u32 units):
//  WINBUF[2]: [0,8192)   (buf p at p*4096: hi +0, lo +2048)
//  WOUT:      [8192,12288)  (hi 8192, lo 10240)
//  UHI [12288,14592) ULO [14592,16896)
//  SH  [16896,19200) SL  [19200,21504)
#define OFF_WOUT 8192
#define OFF_UHI  12288
#define OFF_ULO  14592
#define OFF_SH   16896
#define OFF_SL   19200
#define SMEM_U32 21504

__global__ void __launch_bounds__(256, 2)
main_kernel(const float* __restrict__ u,
            const float* __restrict__ noise,
            const float* __restrict__ bias,
            float* __restrict__ out) {
    extern __shared__ unsigned smu[];
    unsigned* WINB = smu;
    unsigned* W2h  = smu + OFF_WOUT;
    unsigned* W2l  = smu + OFF_WOUT + 2048;
    unsigned* u_hi = smu + OFF_UHI;
    unsigned* u_lo = smu + OFF_ULO;
    unsigned* S_h  = smu + OFF_SH;
    unsigned* S_l  = smu + OFF_SL;
    __half* SHh = (__half*)S_h;
    __half* SLh = (__half*)S_l;

    int tid  = threadIdx.x;
    int lane = tid & 31;
    int w    = tid >> 5;
    int qq   = lane & 3;
    int rr   = lane >> 2;

    int t  = blockIdx.x >> 1;
    int nb = (blockIdx.x & 1) * NB;

    float* xsout = out + (size_t)T_STEPS * DO * BATCH;

    // ---- prologue: stage u[t] (this block's 64 cols) + win chunk 0 ----
    {
        const float* ut = u + (size_t)t * DI * BATCH + nb;
#pragma unroll
        for (int i = 0; i < 4; ++i) {
            int idx = tid + i * 256;        // 0..1023
            int dp  = idx >> 5;             // 0..31
            int b2  = (idx & 31) * 2;       // 0..62
            float2 ra = *(const float2*)(ut + (2 * dp) * BATCH + b2);
            float2 rb = *(const float2*)(ut + (2 * dp + 1) * BATCH + b2);
            float h00, l00, h10, l10, h01, l01, h11, l11;
            sp16(ra.x, h00, l00); sp16(rb.x, h10, l10);
            sp16(ra.y, h01, l01); sp16(rb.y, h11, l11);
            *(uint2*)(u_hi + dp * USTR + b2) = make_uint2(packh2(h00, h10), packh2(h01, h11));
            *(uint2*)(u_lo + dp * USTR + b2) = make_uint2(packh2(l00, l10), packh2(l01, l11));
        }
        const uint4* gh = ((const uint4*)g_win_h);
        const uint4* gl = ((const uint4*)g_win_l);
#pragma unroll
        for (int i = 0; i < 2; ++i) {
            ((uint4*)WINB)[tid + i * 256]          = gh[tid + i * 256];
            ((uint4*)(WINB + 2048))[tid + i * 256] = gl[tid + i * 256];
        }
    }

    float C2[4][4];
#pragma unroll
    for (int a = 0; a < 4; ++a)
#pragma unroll
        for (int q = 0; q < 4; ++q) C2[a][q] = 0.0f;

    for (int c = 0; c < NCHUNK; ++c) {
        __syncthreads();   // sync_a: GEMM2(c-1) done everywhere; staged data visible

        // ---- stage wout(c) and win(c+1); overlaps GEMM1+epilogue below ----
        {
            const uint4* goh = ((const uint4*)g_wout_h) + (size_t)c * 512;
            const uint4* gol = ((const uint4*)g_wout_l) + (size_t)c * 512;
#pragma unroll
            for (int i = 0; i < 2; ++i) {
                ((uint4*)W2h)[tid + i * 256] = goh[tid + i * 256];
                ((uint4*)W2l)[tid + i * 256] = gol[tid + i * 256];
            }
            if (c + 1 < NCHUNK) {
                unsigned* dsth = WINB + ((c + 1) & 1) * 4096;
                const uint4* gh = ((const uint4*)g_win_h) + (size_t)(c + 1) * 512;
                const uint4* gl = ((const uint4*)g_win_l) + (size_t)(c + 1) * 512;
#pragma unroll
                for (int i = 0; i < 2; ++i) {
                    ((uint4*)dsth)[tid + i * 256]          = gh[tid + i * 256];
                    ((uint4*)(dsth + 2048))[tid + i * 256] = gl[tid + i * 256];
                }
            }
        }

        // ---- GEMM1: inp = win_chunk @ u, fp16 3-pass ----
        const unsigned* A1h = WINB + (c & 1) * 4096;
        const unsigned* A1l = A1h + 2048;
        float C1[4][4];
#pragma unroll
        for (int a = 0; a < 4; ++a)
#pragma unroll
            for (int q = 0; q < 4; ++q) C1[a][q] = 0.0f;

#pragma unroll
        for (int kt = 0; kt < 4; ++kt) {
            int n = w * 8 + rr;
            unsigned bh0 = u_hi[(kt * 8 + qq) * USTR + n];
            unsigned bh1 = u_hi[(kt * 8 + 4 + qq) * USTR + n];
            unsigned bl0 = u_lo[(kt * 8 + qq) * USTR + n];
            unsigned bl1 = u_lo[(kt * 8 + 4 + qq) * USTR + n];
#pragma unroll
            for (int mt = 0; mt < 4; ++mt) {
                uint4 ah = *(const uint4*)(A1h + ((kt * 4 + mt) * 32 + lane) * 4);
                uint4 al = *(const uint4*)(A1l + ((kt * 4 + mt) * 32 + lane) * 4);
                mma_f16(C1[mt][0], C1[mt][1], C1[mt][2], C1[mt][3],
                        ah.x, ah.y, ah.z, ah.w, bh0, bh1);
                mma_f16(C1[mt][0], C1[mt][1], C1[mt][2], C1[mt][3],
                        ah.x, ah.y, ah.z, ah.w, bl0, bl1);
                mma_f16(C1[mt][0], C1[mt][1], C1[mt][2], C1[mt][3],
                        al.x, al.y, al.z, al.w, bh0, bh1);
            }
        }

        // ---- epilogue: xs = inp + base + noise; write xs; S = fp16 hi/lo(sigm) ----
        int n0 = nb + w * 8 + 2 * qq;
        int nl = w * 8 + 2 * qq;
#pragma unroll
        for (int mt = 0; mt < 4; ++mt) {
#pragma unroll
            for (int hh = 0; hh < 2; ++hh) {
                int rl = mt * 16 + hh * 8 + rr;
                int hg = c * HC + rl;
                size_t gi = ((size_t)t * DH + hg) * BATCH + n0;
                float2 nz = *(const float2*)(noise + gi);
                float2 bs = *(const float2*)(g_base + (size_t)hg * BATCH + n0);
                float x0 = C1[mt][hh * 2]     + nz.x + bs.x;
                float x1 = C1[mt][hh * 2 + 1] + nz.y + bs.y;
                *(float2*)(xsout + gi) = make_float2(x0, x1);
                float s0h, s0l, s1h, s1l;
                sp16(sigm(x0), s0h, s0l);
                sp16(sigm(x1), s1h, s1l);
                int w0 = (rl >> 1) * USTR + nl;
                int par = rl & 1;
                SHh[w0 * 2 + par]       = __float2half_rn(s0h);
                SHh[(w0 + 1) * 2 + par] = __float2half_rn(s1h);
                SLh[w0 * 2 + par]       = __float2half_rn(s0l);
                SLh[(w0 + 1) * 2 + par] = __float2half_rn(s1l);
            }
        }
        __syncthreads();   // sync_b: S + wout ready

        // ---- GEMM2: out += wout_chunk @ s, fp16 3-pass ----
#pragma unroll
        for (int kt = 0; kt < 4; ++kt) {
            int n = w * 8 + rr;
            unsigned sh0 = S_h[(kt * 8 + qq) * USTR + n];
            unsigned sh1 = S_h[(kt * 8 + 4 + qq) * USTR + n];
            unsigned sl0 = S_l[(kt * 8 + qq) * USTR + n];
            unsigned sl1 = S_l[(kt * 8 + 4 + qq) * USTR + n];
#pragma unroll
            for (int mt = 0; mt < 4; ++mt) {
                uint4 ah = *(const uint4*)(W2h + ((kt * 4 + mt) * 32 + lane) * 4);
                uint4 al = *(const uint4*)(W2l + ((kt * 4 + mt) * 32 + lane) * 4);
                mma_f16(C2[mt][0], C2[mt][1], C2[mt][2], C2[mt][3],
                        ah.x, ah.y, ah.z, ah.w, sh0, sh1);
                mma_f16(C2[mt][0], C2[mt][1], C2[mt][2], C2[mt][3],
                        ah.x, ah.y, ah.z, ah.w, sl0, sl1);
                mma_f16(C2[mt][0], C2[mt][1], C2[mt][2], C2[mt][3],
                        al.x, al.y, al.z, al.w, sh0, sh1);
            }
        }
    }

    // ---- write outputs[t] ----
    int n0 = nb + w * 8 + 2 * qq;
#pragma unroll
    for (int mt = 0; mt < 4; ++mt) {
        int o0 = mt * 16 + rr;
        float bv0 = __ldg(bias + o0);
        float bv8 = __ldg(bias + o0 + 8);
        *(float2*)(out + ((size_t)t * DO + o0) * BATCH + n0) =
            make_float2(C2[mt][0] + bv0, C2[mt][1] + bv0);
        *(float2*)(out + ((size_t)t * DO + o0 + 8) * BATCH + n0) =
            make_float2(C2[mt][2] + bv8, C2[mt][3] + bv8);
    }
}

extern "C" void kernel_launch(void* const* d_in, const int* in_sizes, int n_in,
                              void* d_out, int out_size) {
    const float* u     = (const float*)d_in[0];
    const float* r0    = (const float*)d_in[1];
    const float* noise = (const float*)d_in[2];
    const float* win   = (const float*)d_in[3];
    const float* w_    = (const float*)d_in[4];
    // d_in[5] = m_diag: unused — |_w * (+-1)| == |_w|
    const float* wout  = (const float*)d_in[6];
    const float* bias  = (const float*)d_in[7];
    const float* taus  = (const float*)d_in[8];
    float* out = (float*)d_out;

    const int base_smem = (128 * 128 + 16 * 128) * 4;
    const int main_smem = SMEM_U32 * 4;   // 86016 B -> 2 blocks/SM
    cudaFuncSetAttribute(base_kernel, cudaFuncAttributeMaxDynamicSharedMemorySize, base_smem);
    cudaFuncSetAttribute(main_kernel, cudaFuncAttributeMaxDynamicSharedMemorySize, main_smem);

    sig_kernel<<<256, 256>>>(r0);
    base_kernel<<<DH / 16, 256, base_smem>>>(r0, w_, taus);
    pack_win_kernel<<<64, 256>>>(win);
    pack_wout_kernel<<<64, 256>>>(wout);
    main_kernel<<<2 * T_STEPS, 256, main_smem>>>(u, noise, bias, out);
}

// round 5
// speedup vs baseline: 1.9888x; 1.6355x over previous
#include <cuda_runtime.h>
#include <cuda_fp16.h>
#include <cstdint>
#include <cstddef>

#define T_STEPS 512
#define DH      2048
#define DI      64
#define DO      64
#define BATCH   128
#define HC      64
#define NCHUNK  (DH / HC)        // 32
#define NB      64               // batch cols per block
#define USTR    72               // u32 stride for 64-wide half2 k-pair arrays

// ---- device scratch ----
__device__ float    g_base[DH * BATCH];
__device__ unsigned g_win_h[NCHUNK * 2048];    // fp16x2 A-fragments (hi)
__device__ unsigned g_wout_h[NCHUNK * 2048];

// ---------- helpers ----------
union F2U { unsigned long long u; float2 f; };

__device__ __forceinline__ unsigned long long pack2(float w) {
    unsigned int wi = __float_as_uint(w);
    unsigned long long r;
    asm("mov.b64 %0, {%1, %1};" : "=l"(r) : "r"(wi));
    return r;
}
__device__ __forceinline__ void fma2(unsigned long long& d,
                                     unsigned long long a,
                                     unsigned long long b) {
    asm("fma.rn.f32x2 %0, %1, %2, %0;" : "+l"(d) : "l"(a), "l"(b));
}
__device__ __forceinline__ float sigm(float x) {
    return __fdividef(1.0f, 1.0f + __expf(-x));
}
__device__ __forceinline__ void sp16(float x, float& h, float& l) {
    h = __half2float(__float2half_rn(x));
    l = x - h;
}
__device__ __forceinline__ unsigned packh2(float a, float b) {
    __half2 h = __floats2half2_rn(a, b);
    return *(unsigned*)&h;
}
__device__ __forceinline__ void mma_f16(float& c0, float& c1, float& c2, float& c3,
                                        unsigned a0, unsigned a1, unsigned a2, unsigned a3,
                                        unsigned b0, unsigned b1) {
    asm volatile("mma.sync.aligned.m16n8k16.row.col.f32.f16.f16.f32 "
                 "{%0,%1,%2,%3}, {%4,%5,%6,%7}, {%8,%9}, {%0,%1,%2,%3};"
                 : "+f"(c0), "+f"(c1), "+f"(c2), "+f"(c3)
                 : "r"(a0), "r"(a1), "r"(a2), "r"(a3), "r"(b0), "r"(b1));
}

// ---------- kernel 1: base = (1-a)*r0 + a*(|W| @ sigmoid(r0)) ----------
__global__ void __launch_bounds__(256, 2)
base_kernel(const float* __restrict__ r0,
            const float* __restrict__ w_,
            const float* __restrict__ taus) {
    extern __shared__ float sm[];
    float* sr_s = sm;              // 128 x 128 sigmoid(r0) chunk
    float* w_s  = sm + 128 * 128;  // 16 x 128

    int tid = threadIdx.x;
    int cp  = tid & 31;
    int rg  = tid >> 5;
    int hbase = blockIdx.x * 16;

    unsigned long long acc[2][2] = {{0ull, 0ull}, {0ull, 0ull}};

    for (int kc = 0; kc < DH / 128; ++kc) {
        int k0 = kc * 128;
        __syncthreads();
        {
            const float4* src = (const float4*)(r0 + (size_t)k0 * BATCH);
            float4* dst = (float4*)sr_s;
#pragma unroll
            for (int i = 0; i < 16; ++i) {
                float4 v = src[tid + i * 256];
                v.x = sigm(v.x); v.y = sigm(v.y);
                v.z = sigm(v.z); v.w = sigm(v.w);
                dst[tid + i * 256] = v;
            }
        }
#pragma unroll
        for (int j = 0; j < 2; ++j) {
            int e  = j * 1024 + tid * 4;
            int r  = e >> 7;
            int kk = e & 127;
            float4 wv = *(const float4*)(w_ + (size_t)(hbase + r) * DH + k0 + kk);
            wv.x = fabsf(wv.x); wv.y = fabsf(wv.y);
            wv.z = fabsf(wv.z); wv.w = fabsf(wv.w);
            *(float4*)(w_s + r * 128 + kk) = wv;
        }
        __syncthreads();

#pragma unroll 4
        for (int kk = 0; kk < 128; ++kk) {
            ulonglong2 sv = *(const ulonglong2*)(sr_s + kk * BATCH + 4 * cp);
#pragma unroll
            for (int r = 0; r < 2; ++r) {
                unsigned long long pw = pack2(w_s[(rg * 2 + r) * 128 + kk]);
                fma2(acc[r][0], pw, sv.x);
                fma2(acc[r][1], pw, sv.y);
            }
        }
    }

#pragma unroll
    for (int r = 0; r < 2; ++r) {
        int h = hbase + rg * 2 + r;
        float alpha = 1.0f / taus[h];
        float om = 1.0f - alpha;
        float4 rv = *(const float4*)(r0 + (size_t)h * BATCH + 4 * cp);
        F2U lo, hi; lo.u = acc[r][0]; hi.u = acc[r][1];
        float4 o;
        o.x = om * rv.x + alpha * lo.f.x;
        o.y = om * rv.y + alpha * lo.f.y;
        o.z = om * rv.z + alpha * hi.f.x;
        o.w = om * rv.w + alpha * hi.f.y;
        *(float4*)(g_base + (size_t)h * BATCH + 4 * cp) = o;
    }
}

// ---------- kernel 2: pack win + wout into fp16 A-fragments (hi only) ----------
__global__ void pack_kernel(const float* __restrict__ win,
                            const float* __restrict__ wout) {
    int tg0 = blockIdx.x * blockDim.x + threadIdx.x;   // 0..32767
    int tg  = tg0 & 16383;
    int lane = tg & 31;
    int mt = (tg >> 5) & 3;
    int kt = (tg >> 7) & 3;
    int c  = tg >> 9;
    uint4 oh;
    if (tg0 < 16384) {
        int r0 = (c * 4 + mt) * 16 + (lane >> 2);
        int k0 = kt * 16 + 2 * (lane & 3);
        oh.x = packh2(win[r0 * DI + k0],           win[r0 * DI + k0 + 1]);
        oh.y = packh2(win[(r0 + 8) * DI + k0],     win[(r0 + 8) * DI + k0 + 1]);
        oh.z = packh2(win[r0 * DI + k0 + 8],       win[r0 * DI + k0 + 9]);
        oh.w = packh2(win[(r0 + 8) * DI + k0 + 8], win[(r0 + 8) * DI + k0 + 9]);
        *(uint4*)(g_win_h + (size_t)tg * 4) = oh;
    } else {
        int r0 = mt * 16 + (lane >> 2);
        int k0 = c * HC + kt * 16 + 2 * (lane & 3);
        oh.x = packh2(wout[r0 * DH + k0],           wout[r0 * DH + k0 + 1]);
        oh.y = packh2(wout[(r0 + 8) * DH + k0],     wout[(r0 + 8) * DH + k0 + 1]);
        oh.z = packh2(wout[r0 * DH + k0 + 8],       wout[r0 * DH + k0 + 9]);
        oh.w = packh2(wout[(r0 + 8) * DH + k0 + 8], wout[(r0 + 8) * DH + k0 + 9]);
        *(uint4*)(g_wout_h + (size_t)tg * 4) = oh;
    }
}

// ---------- main kernel ----------
// grid 1024: block = (t, batch-half). 8 warps; warp w owns 8 n-cols.
// smem (u32 units):
//  WINB[2]  [0,4096)      (2048 each)
//  WOUTB[2] [4096,8192)
//  UHI [8192,10496)  ULO [10496,12800)
//  SH[2] [12800,17408)    (2304 each)
#define OFF_WOUT 4096
#define OFF_UHI  8192
#define OFF_ULO  10496
#define OFF_SH   12800
#define SMEM_U32 17408

__global__ void __launch_bounds__(256, 2)
main_kernel(const float* __restrict__ u,
            const float* __restrict__ noise,
            const float* __restrict__ bias,
            float* __restrict__ out) {
    extern __shared__ unsigned smu[];
    unsigned* WINB   = smu;
    unsigned* WOUTB  = smu + OFF_WOUT;
    unsigned* u_hi   = smu + OFF_UHI;
    unsigned* u_lo   = smu + OFF_ULO;
    unsigned* S_base = smu + OFF_SH;

    int tid  = threadIdx.x;
    int lane = tid & 31;
    int w    = tid >> 5;
    int qq   = lane & 3;
    int rr   = lane >> 2;

    int t  = blockIdx.x >> 1;
    int nb = (blockIdx.x & 1) * NB;

    float* xsout = out + (size_t)T_STEPS * DO * BATCH;

    // ---- prologue: stage u[t] slice, win[0], wout[0] ----
    {
        const float* ut = u + (size_t)t * DI * BATCH + nb;
#pragma unroll
        for (int i = 0; i < 4; ++i) {
            int idx = tid + i * 256;        // 0..1023
            int dp  = idx >> 5;             // 0..31
            int b2  = (idx & 31) * 2;       // 0..62
            float2 ra = *(const float2*)(ut + (2 * dp) * BATCH + b2);
            float2 rb = *(const float2*)(ut + (2 * dp + 1) * BATCH + b2);
            float h00, l00, h10, l10, h01, l01, h11, l11;
            sp16(ra.x, h00, l00); sp16(rb.x, h10, l10);
            sp16(ra.y, h01, l01); sp16(rb.y, h11, l11);
            *(uint2*)(u_hi + dp * USTR + b2) = make_uint2(packh2(h00, h10), packh2(h01, h11));
            *(uint2*)(u_lo + dp * USTR + b2) = make_uint2(packh2(l00, l10), packh2(l01, l11));
        }
        ((uint4*)WINB)[tid]        = ((const uint4*)g_win_h)[tid];
        ((uint4*)WINB)[tid + 256]  = ((const uint4*)g_win_h)[tid + 256];
        ((uint4*)WOUTB)[tid]       = ((const uint4*)g_wout_h)[tid];
        ((uint4*)WOUTB)[tid + 256] = ((const uint4*)g_wout_h)[tid + 256];
    }

    float C2[4][4];
#pragma unroll
    for (int a = 0; a < 4; ++a)
#pragma unroll
        for (int q = 0; q < 4; ++q) C2[a][q] = 0.0f;

    int n0 = nb + w * 8 + 2 * qq;     // global batch col (pair base)
    int nl = w * 8 + 2 * qq;          // local batch col
    int n  = w * 8 + rr;              // B-fragment col

    __syncthreads();

    for (int c = 0; c < NCHUNK; ++c) {
        // ---- prefetch noise + base for this chunk into registers ----
        float2 nz[8], bs[8];
#pragma unroll
        for (int mt = 0; mt < 4; ++mt)
#pragma unroll
            for (int hh = 0; hh < 2; ++hh) {
                int hg = c * HC + mt * 16 + hh * 8 + rr;
                size_t gi = ((size_t)t * DH + hg) * BATCH + n0;
                nz[mt * 2 + hh] = *(const float2*)(noise + gi);
                bs[mt * 2 + hh] = *(const float2*)(g_base + (size_t)hg * BATCH + n0);
            }

        // ---- stage win[c+1] (pre-sync section) ----
        if (c + 1 < NCHUNK) {
            uint4* dst = (uint4*)(WINB + ((c + 1) & 1) * 2048);
            const uint4* src = ((const uint4*)g_win_h) + (size_t)(c + 1) * 512;
            dst[tid]       = src[tid];
            dst[tid + 256] = src[tid + 256];
        }

        // ---- GEMM1: inp = win_h @ (u_h + u_l), 2-pass fp16 ----
        const unsigned* A1 = WINB + (c & 1) * 2048;
        float C1[4][4];
#pragma unroll
        for (int a = 0; a < 4; ++a)
#pragma unroll
            for (int q = 0; q < 4; ++q) C1[a][q] = 0.0f;

#pragma unroll
        for (int kt = 0; kt < 4; ++kt) {
            unsigned bh0 = u_hi[(kt * 8 + qq) * USTR + n];
            unsigned bh1 = u_hi[(kt * 8 + 4 + qq) * USTR + n];
            unsigned bl0 = u_lo[(kt * 8 + qq) * USTR + n];
            unsigned bl1 = u_lo[(kt * 8 + 4 + qq) * USTR + n];
#pragma unroll
            for (int mt = 0; mt < 4; ++mt) {
                uint4 ah = *(const uint4*)(A1 + ((kt * 4 + mt) * 32 + lane) * 4);
                mma_f16(C1[mt][0], C1[mt][1], C1[mt][2], C1[mt][3],
                        ah.x, ah.y, ah.z, ah.w, bh0, bh1);
                mma_f16(C1[mt][0], C1[mt][1], C1[mt][2], C1[mt][3],
                        ah.x, ah.y, ah.z, ah.w, bl0, bl1);
            }
        }

        // ---- epilogue: xs = inp + base + noise; write xs; S = fp16(sigm(xs)) ----
        __half* SH = (__half*)(S_base + (c & 1) * 2304);
#pragma unroll
        for (int mt = 0; mt < 4; ++mt) {
#pragma unroll
            for (int hh = 0; hh < 2; ++hh) {
                int rl = mt * 16 + hh * 8 + rr;
                int hg = c * HC + rl;
                size_t gi = ((size_t)t * DH + hg) * BATCH + n0;
                float2 nb2 = nz[mt * 2 + hh];
                float2 bb2 = bs[mt * 2 + hh];
                float x0 = C1[mt][hh * 2]     + nb2.x + bb2.x;
                float x1 = C1[mt][hh * 2 + 1] + nb2.y + bb2.y;
                *(float2*)(xsout + gi) = make_float2(x0, x1);
                int w0 = (rl >> 1) * USTR + nl;
                int par = rl & 1;
                SH[w0 * 2 + par]       = __float2half_rn(sigm(x0));
                SH[(w0 + 1) * 2 + par] = __float2half_rn(sigm(x1));
            }
        }
        __syncthreads();   // the one sync per chunk

        // ---- stage wout[c+1] (post-sync section) ----
        if (c + 1 < NCHUNK) {
            uint4* dst = (uint4*)(WOUTB + ((c + 1) & 1) * 2048);
            const uint4* src = ((const uint4*)g_wout_h) + (size_t)(c + 1) * 512;
            dst[tid]       = src[tid];
            dst[tid + 256] = src[tid + 256];
        }

        // ---- GEMM2: out += wout_h @ s_h, single-pass fp16 ----
        const unsigned* A2  = WOUTB + (c & 1) * 2048;
        const unsigned* S_u = S_base + (c & 1) * 2304;
#pragma unroll
        for (int kt = 0; kt < 4; ++kt) {
            unsigned sh0 = S_u[(kt * 8 + qq) * USTR + n];
            unsigned sh1 = S_u[(kt * 8 + 4 + qq) * USTR + n];
#pragma unroll
            for (int mt = 0; mt < 4; ++mt) {
                uint4 aw = *(const uint4*)(A2 + ((kt * 4 + mt) * 32 + lane) * 4);
                mma_f16(C2[mt][0], C2[mt][1], C2[mt][2], C2[mt][3],
                        aw.x, aw.y, aw.z, aw.w, sh0, sh1);
            }
        }
    }

    // ---- write outputs[t] ----
#pragma unroll
    for (int mt = 0; mt < 4; ++mt) {
        int o0 = mt * 16 + rr;
        float bv0 = __ldg(bias + o0);
        float bv8 = __ldg(bias + o0 + 8);
        *(float2*)(out + ((size_t)t * DO + o0) * BATCH + n0) =
            make_float2(C2[mt][0] + bv0, C2[mt][1] + bv0);
        *(float2*)(out + ((size_t)t * DO + o0 + 8) * BATCH + n0) =
            make_float2(C2[mt][2] + bv8, C2[mt][3] + bv8);
    }
}

extern "C" void kernel_launch(void* const* d_in, const int* in_sizes, int n_in,
                              void* d_out, int out_size) {
    const float* u     = (const float*)d_in[0];
    const float* r0    = (const float*)d_in[1];
    const float* noise = (const float*)d_in[2];
    const float* win   = (const float*)d_in[3];
    const float* w_    = (const float*)d_in[4];
    // d_in[5] = m_diag: unused — |_w * (+-1)| == |_w|
    const float* wout  = (const float*)d_in[6];
    const float* bias  = (const float*)d_in[7];
    const float* taus  = (const float*)d_in[8];
    float* out = (float*)d_out;

    const int base_smem = (128 * 128 + 16 * 128) * 4;   // 73728
    const int main_smem = SMEM_U32 * 4;                 // 69632 -> 2 blocks/SM
    cudaFuncSetAttribute(base_kernel, cudaFuncAttributeMaxDynamicSharedMemorySize, base_smem);
    cudaFuncSetAttribute(main_kernel, cudaFuncAttributeMaxDynamicSharedMemorySize, main_smem);

    base_kernel<<<DH / 16, 256, base_smem>>>(r0, w_, taus);
    pack_kernel<<<128, 256>>>(win, wout);
    main_kernel<<<2 * T_STEPS, 256, main_smem>>>(u, noise, bias, out);
}

// round 6
// speedup vs baseline: 2.3048x; 1.1589x over previous
#include <cuda_runtime.h>
#include <cuda_fp16.h>
#include <cstdint>
#include <cstddef>

#define T_STEPS 512
#define DH      2048
#define DI      64
#define DO      64
#define BATCH   128
#define HC      64
#define NCHUNK  (DH / HC)        // 32
#define NB      64               // batch cols per block
#define USTR    72               // u32 stride for 64-wide half2 k-pair arrays

// ---- device scratch ----
__device__ float    g_base[DH * BATCH];            // 1 MB
__device__ float    g_part[4 * DH * BATCH];        // 4 MB K-quarter partials
__device__ unsigned g_win_h[NCHUNK * 2048];        // fp16x2 win A-fragments
__device__ unsigned g_wout_h[NCHUNK * 2048];       // fp16x2 wout A-fragments
__device__ unsigned g_wfrag[4 * 32 * 32 * 4 * 32 * 4]; // |w| fp16 A-frags, 8 MB
__device__ unsigned g_spk[1024 * 128];             // sigmoid(r0) fp16 k-pair, 512 KB

// ---------- helpers ----------
__device__ __forceinline__ float sigm(float x) {
    return __fdividef(1.0f, 1.0f + __expf(-x));
}
__device__ __forceinline__ void sp16(float x, float& h, float& l) {
    h = __half2float(__float2half_rn(x));
    l = x - h;
}
__device__ __forceinline__ unsigned packh2(float a, float b) {
    __half2 h = __floats2half2_rn(a, b);   // a -> low half
    return *(unsigned*)&h;
}
__device__ __forceinline__ void mma_f16(float& c0, float& c1, float& c2, float& c3,
                                        unsigned a0, unsigned a1, unsigned a2, unsigned a3,
                                        unsigned b0, unsigned b1) {
    asm volatile("mma.sync.aligned.m16n8k16.row.col.f32.f16.f16.f32 "
                 "{%0,%1,%2,%3}, {%4,%5,%6,%7}, {%8,%9}, {%0,%1,%2,%3};"
                 : "+f"(c0), "+f"(c1), "+f"(c2), "+f"(c3)
                 : "r"(a0), "r"(a1), "r"(a2), "r"(a3), "r"(b0), "r"(b1));
}

// ---------- kernel 1: all packing (win, wout, |w|, sigmoid(r0)) ----------
// blocks [0,64):   win   -> g_win_h
// blocks [64,128): wout  -> g_wout_h
// blocks [128,384): sigmoid(r0) -> g_spk
// blocks [384,2432): |w| -> g_wfrag
__global__ void pack_all_kernel(const float* __restrict__ win,
                                const float* __restrict__ wout,
                                const float* __restrict__ r0,
                                const float* __restrict__ w_) {
    int bx = blockIdx.x;
    int tid = threadIdx.x;
    if (bx < 128) {
        int tg = (bx & 63) * 256 + tid;       // 0..16383
        int lane = tg & 31;
        int mt = (tg >> 5) & 3;
        int kt = (tg >> 7) & 3;
        int c  = tg >> 9;
        uint4 oh;
        if (bx < 64) {
            int r = (c * 4 + mt) * 16 + (lane >> 2);
            int k0 = kt * 16 + 2 * (lane & 3);
            oh.x = packh2(win[r * DI + k0],           win[r * DI + k0 + 1]);
            oh.y = packh2(win[(r + 8) * DI + k0],     win[(r + 8) * DI + k0 + 1]);
            oh.z = packh2(win[r * DI + k0 + 8],       win[r * DI + k0 + 9]);
            oh.w = packh2(win[(r + 8) * DI + k0 + 8], win[(r + 8) * DI + k0 + 9]);
            *(uint4*)(g_win_h + (size_t)tg * 4) = oh;
        } else {
            int r = mt * 16 + (lane >> 2);
            int k0 = c * HC + kt * 16 + 2 * (lane & 3);
            oh.x = packh2(wout[r * DH + k0],           wout[r * DH + k0 + 1]);
            oh.y = packh2(wout[(r + 8) * DH + k0],     wout[(r + 8) * DH + k0 + 1]);
            oh.z = packh2(wout[r * DH + k0 + 8],       wout[r * DH + k0 + 9]);
            oh.w = packh2(wout[(r + 8) * DH + k0 + 8], wout[(r + 8) * DH + k0 + 9]);
            *(uint4*)(g_wout_h + (size_t)tg * 4) = oh;
        }
    } else if (bx < 384) {
        int i = (bx - 128) * 256 + tid;       // 0..65535
        int bp = i & 63;                       // b pair
        int kp = i >> 6;                       // 0..1023
        float2 ra = *(const float2*)(r0 + (size_t)(2 * kp) * BATCH + 2 * bp);
        float2 rb = *(const float2*)(r0 + (size_t)(2 * kp + 1) * BATCH + 2 * bp);
        uint2 o;
        o.x = packh2(sigm(ra.x), sigm(rb.x));
        o.y = packh2(sigm(ra.y), sigm(rb.y));
        *(uint2*)(g_spk + (size_t)kp * BATCH + 2 * bp) = o;
    } else {
        int tg = (bx - 384) * 256 + tid;      // 0..524287
        int lane = tg & 31;
        int mt = (tg >> 5) & 3;
        int kt = (tg >> 7) & 31;
        int hc = (tg >> 12) & 31;
        int kq = tg >> 17;
        int r  = hc * HC + mt * 16 + (lane >> 2);
        int k0 = kq * 512 + kt * 16 + 2 * (lane & 3);
        uint4 oh;
        oh.x = packh2(fabsf(w_[(size_t)r * DH + k0]),
                      fabsf(w_[(size_t)r * DH + k0 + 1]));
        oh.y = packh2(fabsf(w_[(size_t)(r + 8) * DH + k0]),
                      fabsf(w_[(size_t)(r + 8) * DH + k0 + 1]));
        oh.z = packh2(fabsf(w_[(size_t)r * DH + k0 + 8]),
                      fabsf(w_[(size_t)r * DH + k0 + 9]));
        oh.w = packh2(fabsf(w_[(size_t)(r + 8) * DH + k0 + 8]),
                      fabsf(w_[(size_t)(r + 8) * DH + k0 + 9]));
        *(uint4*)(g_wfrag + (size_t)tg * 4) = oh;
    }
}

// ---------- kernel 2: base GEMM partials: g_part[kq] = |W|[:,kq] @ s[kq] ----------
// grid 256 = kq(4) x hc(32) x nh(2). No smem, no syncs. fp16 single-pass.
__global__ void __launch_bounds__(256)
base_gemm_kernel() {
    int bx = blockIdx.x;
    int kq = bx >> 6;
    int hc = (bx >> 1) & 31;
    int nh = bx & 1;

    int tid  = threadIdx.x;
    int lane = tid & 31;
    int w    = tid >> 5;
    int qq   = lane & 3;
    int rr   = lane >> 2;
    int n    = nh * NB + w * 8 + rr;

    float C[4][4];
#pragma unroll
    for (int a = 0; a < 4; ++a)
#pragma unroll
        for (int q = 0; q < 4; ++q) C[a][q] = 0.0f;

    const uint4* Af = ((const uint4*)g_wfrag) + ((size_t)(kq * 32 + hc) * 32) * 128;

#pragma unroll 4
    for (int kt = 0; kt < 32; ++kt) {
        int kp = kq * 256 + kt * 8;
        unsigned b0 = g_spk[(size_t)(kp + qq) * BATCH + n];
        unsigned b1 = g_spk[(size_t)(kp + 4 + qq) * BATCH + n];
#pragma unroll
        for (int mt = 0; mt < 4; ++mt) {
            uint4 a4 = Af[(kt * 4 + mt) * 32 + lane];
            mma_f16(C[mt][0], C[mt][1], C[mt][2], C[mt][3],
                    a4.x, a4.y, a4.z, a4.w, b0, b1);
        }
    }

    float* dst = g_part + (size_t)kq * DH * BATCH;
    int n0 = nh * NB + w * 8 + 2 * qq;
#pragma unroll
    for (int mt = 0; mt < 4; ++mt)
#pragma unroll
        for (int hh = 0; hh < 2; ++hh) {
            int h = hc * HC + mt * 16 + hh * 8 + rr;
            *(float2*)(dst + (size_t)h * BATCH + n0) =
                make_float2(C[mt][hh * 2], C[mt][hh * 2 + 1]);
        }
}

// ---------- kernel 3: base = (1-a)*r0 + a*(p0+p1+p2+p3) ----------
__global__ void base_reduce_kernel(const float* __restrict__ r0,
                                   const float* __restrict__ taus) {
    int i4 = (blockIdx.x * blockDim.x + threadIdx.x) * 4;   // 256x256x4
    int h  = i4 >> 7;
    float alpha = 1.0f / taus[h];
    float om = 1.0f - alpha;
    float4 rv = *(const float4*)(r0 + i4);
    float4 p0 = *(const float4*)(g_part + i4);
    float4 p1 = *(const float4*)(g_part + DH * BATCH + i4);
    float4 p2 = *(const float4*)(g_part + 2 * DH * BATCH + i4);
    float4 p3 = *(const float4*)(g_part + 3 * DH * BATCH + i4);
    float4 o;
    o.x = om * rv.x + alpha * (p0.x + p1.x + p2.x + p3.x);
    o.y = om * rv.y + alpha * (p0.y + p1.y + p2.y + p3.y);
    o.z = om * rv.z + alpha * (p0.z + p1.z + p2.z + p3.z);
    o.w = om * rv.w + alpha * (p0.w + p1.w + p2.w + p3.w);
    *(float4*)(g_base + i4) = o;
}

// ---------- kernel 4: main, 2 timesteps per block ----------
// grid 512 = t-pair(256) x batch-half(2). 8 warps; warp w owns 8 n-cols.
// smem (u32): WINB[2] 0..4096 | WOUTB[2] 4096..8192 |
//   UH0 8192 UL0 10496 UH1 12800 UL1 15104 (2304 each) |
//   S0[2] 17408..22016 S1[2] 22016..26624
#define OFF_WOUT 4096
#define OFF_UH0  8192
#define OFF_UL0  10496
#define OFF_UH1  12800
#define OFF_UL1  15104
#define OFF_S0   17408
#define OFF_S1   22016
#define SMEM_U32 26624

__global__ void __launch_bounds__(256, 2)
main_kernel(const float* __restrict__ u,
            const float* __restrict__ noise,
            const float* __restrict__ bias,
            float* __restrict__ out) {
    extern __shared__ unsigned smu[];
    unsigned* WINB  = smu;
    unsigned* WOUTB = smu + OFF_WOUT;

    int tid  = threadIdx.x;
    int lane = tid & 31;
    int w    = tid >> 5;
    int qq   = lane & 3;
    int rr   = lane >> 2;

    int t0 = (blockIdx.x >> 1) * 2;
    int t1 = t0 + 1;
    int nb = (blockIdx.x & 1) * NB;

    float* xsout = out + (size_t)T_STEPS * DO * BATCH;

    // ---- prologue: stage u[t0], u[t1] slices + win[0], wout[0] ----
#pragma unroll
    for (int tt = 0; tt < 2; ++tt) {
        const float* ut = u + (size_t)(t0 + tt) * DI * BATCH + nb;
        unsigned* uh = smu + (tt ? OFF_UH1 : OFF_UH0);
        unsigned* ul = smu + (tt ? OFF_UL1 : OFF_UL0);
#pragma unroll
        for (int i = 0; i < 4; ++i) {
            int idx = tid + i * 256;
            int dp  = idx >> 5;
            int b2  = (idx & 31) * 2;
            float2 ra = *(const float2*)(ut + (2 * dp) * BATCH + b2);
            float2 rb = *(const float2*)(ut + (2 * dp + 1) * BATCH + b2);
            float h00, l00, h10, l10, h01, l01, h11, l11;
            sp16(ra.x, h00, l00); sp16(rb.x, h10, l10);
            sp16(ra.y, h01, l01); sp16(rb.y, h11, l11);
            *(uint2*)(uh + dp * USTR + b2) = make_uint2(packh2(h00, h10), packh2(h01, h11));
            *(uint2*)(ul + dp * USTR + b2) = make_uint2(packh2(l00, l10), packh2(l01, l11));
        }
    }
    ((uint4*)WINB)[tid]        = ((const uint4*)g_win_h)[tid];
    ((uint4*)WINB)[tid + 256]  = ((const uint4*)g_win_h)[tid + 256];
    ((uint4*)WOUTB)[tid]       = ((const uint4*)g_wout_h)[tid];
    ((uint4*)WOUTB)[tid + 256] = ((const uint4*)g_wout_h)[tid + 256];

    float C2a[4][4], C2b[4][4];
#pragma unroll
    for (int a = 0; a < 4; ++a)
#pragma unroll
        for (int q = 0; q < 4; ++q) { C2a[a][q] = 0.0f; C2b[a][q] = 0.0f; }

    int n0 = nb + w * 8 + 2 * qq;
    int nl = w * 8 + 2 * qq;
    int n  = w * 8 + rr;

    __syncthreads();

    for (int c = 0; c < NCHUNK; ++c) {
        // ---- prefetch base (shared) + noise[t0] for this chunk ----
        float2 bs[8], nz[8];
#pragma unroll
        for (int mt = 0; mt < 4; ++mt)
#pragma unroll
            for (int hh = 0; hh < 2; ++hh) {
                int hg = c * HC + mt * 16 + hh * 8 + rr;
                bs[mt * 2 + hh] = *(const float2*)(g_base + (size_t)hg * BATCH + n0);
                nz[mt * 2 + hh] = *(const float2*)(noise + ((size_t)t0 * DH + hg) * BATCH + n0);
            }

        // ---- stage win[c+1] ----
        if (c + 1 < NCHUNK) {
            uint4* dst = (uint4*)(WINB + ((c + 1) & 1) * 2048);
            const uint4* src = ((const uint4*)g_win_h) + (size_t)(c + 1) * 512;
            dst[tid]       = src[tid];
            dst[tid + 256] = src[tid + 256];
        }

        // ---- GEMM1 both t: inp = win_h @ (u_h + u_l) ----
        const unsigned* A1 = WINB + (c & 1) * 2048;
        const unsigned* uh0 = smu + OFF_UH0;
        const unsigned* ul0 = smu + OFF_UL0;
        const unsigned* uh1 = smu + OFF_UH1;
        const unsigned* ul1 = smu + OFF_UL1;
        float C1a[4][4], C1b[4][4];
#pragma unroll
        for (int a = 0; a < 4; ++a)
#pragma unroll
            for (int q = 0; q < 4; ++q) { C1a[a][q] = 0.0f; C1b[a][q] = 0.0f; }

#pragma unroll
        for (int kt = 0; kt < 4; ++kt) {
            int ra = (kt * 8 + qq) * USTR + n;
            int rb = (kt * 8 + 4 + qq) * USTR + n;
            unsigned ah0 = uh0[ra], ah1 = uh0[rb];
            unsigned al0 = ul0[ra], al1 = ul0[rb];
            unsigned bh0 = uh1[ra], bh1 = uh1[rb];
            unsigned bl0 = ul1[ra], bl1 = ul1[rb];
#pragma unroll
            for (int mt = 0; mt < 4; ++mt) {
                uint4 a4 = *(const uint4*)(A1 + ((kt * 4 + mt) * 32 + lane) * 4);
                mma_f16(C1a[mt][0], C1a[mt][1], C1a[mt][2], C1a[mt][3],
                        a4.x, a4.y, a4.z, a4.w, ah0, ah1);
                mma_f16(C1a[mt][0], C1a[mt][1], C1a[mt][2], C1a[mt][3],
                        a4.x, a4.y, a4.z, a4.w, al0, al1);
                mma_f16(C1b[mt][0], C1b[mt][1], C1b[mt][2], C1b[mt][3],
                        a4.x, a4.y, a4.z, a4.w, bh0, bh1);
                mma_f16(C1b[mt][0], C1b[mt][1], C1b[mt][2], C1b[mt][3],
                        a4.x, a4.y, a4.z, a4.w, bl0, bl1);
            }
        }

        // ---- epilogue t0 ----
        __half* SH0 = (__half*)(smu + OFF_S0 + (c & 1) * 2304);
#pragma unroll
        for (int mt = 0; mt < 4; ++mt) {
#pragma unroll
            for (int hh = 0; hh < 2; ++hh) {
                int rl = mt * 16 + hh * 8 + rr;
                int hg = c * HC + rl;
                float2 nn = nz[mt * 2 + hh];
                float2 bb = bs[mt * 2 + hh];
                float x0 = C1a[mt][hh * 2]     + nn.x + bb.x;
                float x1 = C1a[mt][hh * 2 + 1] + nn.y + bb.y;
                *(float2*)(xsout + ((size_t)t0 * DH + hg) * BATCH + n0) = make_float2(x0, x1);
                int w0 = (rl >> 1) * USTR + nl;
                int par = rl & 1;
                SH0[w0 * 2 + par]       = __float2half_rn(sigm(x0));
                SH0[(w0 + 1) * 2 + par] = __float2half_rn(sigm(x1));
            }
        }

        // ---- prefetch noise[t1], then epilogue t1 ----
#pragma unroll
        for (int mt = 0; mt < 4; ++mt)
#pragma unroll
            for (int hh = 0; hh < 2; ++hh) {
                int hg = c * HC + mt * 16 + hh * 8 + rr;
                nz[mt * 2 + hh] = *(const float2*)(noise + ((size_t)t1 * DH + hg) * BATCH + n0);
            }
        __half* SH1 = (__half*)(smu + OFF_S1 + (c & 1) * 2304);
#pragma unroll
        for (int mt = 0; mt < 4; ++mt) {
#pragma unroll
            for (int hh = 0; hh < 2; ++hh) {
                int rl = mt * 16 + hh * 8 + rr;
                int hg = c * HC + rl;
                float2 nn = nz[mt * 2 + hh];
                float2 bb = bs[mt * 2 + hh];
                float x0 = C1b[mt][hh * 2]     + nn.x + bb.x;
                float x1 = C1b[mt][hh * 2 + 1] + nn.y + bb.y;
                *(float2*)(xsout + ((size_t)t1 * DH + hg) * BATCH + n0) = make_float2(x0, x1);
                int w0 = (rl >> 1) * USTR + nl;
                int par = rl & 1;
                SH1[w0 * 2 + par]       = __float2half_rn(sigm(x0));
                SH1[(w0 + 1) * 2 + par] = __float2half_rn(sigm(x1));
            }
        }
        __syncthreads();   // the one sync per chunk

        // ---- stage wout[c+1] ----
        if (c + 1 < NCHUNK) {
            uint4* dst = (uint4*)(WOUTB + ((c + 1) & 1) * 2048);
            const uint4* src = ((const uint4*)g_wout_h) + (size_t)(c + 1) * 512;
            dst[tid]       = src[tid];
            dst[tid + 256] = src[tid + 256];
        }

        // ---- GEMM2 both t: out += wout_h @ s_h ----
        const unsigned* A2 = WOUTB + (c & 1) * 2048;
        const unsigned* S0 = smu + OFF_S0 + (c & 1) * 2304;
        const unsigned* S1 = smu + OFF_S1 + (c & 1) * 2304;
#pragma unroll
        for (int kt = 0; kt < 4; ++kt) {
            int ra = (kt * 8 + qq) * USTR + n;
            int rb = (kt * 8 + 4 + qq) * USTR + n;
            unsigned sa0 = S0[ra], sa1 = S0[rb];
            unsigned sb0 = S1[ra], sb1 = S1[rb];
#pragma unroll
            for (int mt = 0; mt < 4; ++mt) {
                uint4 a4 = *(const uint4*)(A2 + ((kt * 4 + mt) * 32 + lane) * 4);
                mma_f16(C2a[mt][0], C2a[mt][1], C2a[mt][2], C2a[mt][3],
                        a4.x, a4.y, a4.z, a4.w, sa0, sa1);
                mma_f16(C2b[mt][0], C2b[mt][1], C2b[mt][2], C2b[mt][3],
                        a4.x, a4.y, a4.z, a4.w, sb0, sb1);
            }
        }
    }

    // ---- write outputs[t0], outputs[t1] ----
#pragma unroll
    for (int mt = 0; mt < 4; ++mt) {
        int o0 = mt * 16 + rr;
        float bv0 = __ldg(bias + o0);
        float bv8 = __ldg(bias + o0 + 8);
        *(float2*)(out + ((size_t)t0 * DO + o0) * BATCH + n0) =
            make_float2(C2a[mt][0] + bv0, C2a[mt][1] + bv0);
        *(float2*)(out + ((size_t)t0 * DO + o0 + 8) * BATCH + n0) =
            make_float2(C2a[mt][2] + bv8, C2a[mt][3] + bv8);
        *(float2*)(out + ((size_t)t1 * DO + o0) * BATCH + n0) =
            make_float2(C2b[mt][0] + bv0, C2b[mt][1] + bv0);
        *(float2*)(out + ((size_t)t1 * DO + o0 + 8) * BATCH + n0) =
            make_float2(C2b[mt][2] + bv8, C2b[mt][3] + bv8);
    }
}

extern "C" void kernel_launch(void* const* d_in, const int* in_sizes, int n_in,
                              void* d_out, int out_size) {
    const float* u     = (const float*)d_in[0];
    const float* r0    = (const float*)d_in[1];
    const float* noise = (const float*)d_in[2];
    const float* win   = (const float*)d_in[3];
    const float* w_    = (const float*)d_in[4];
    // d_in[5] = m_diag: unused — |_w * (+-1)| == |_w|
    const float* wout  = (const float*)d_in[6];
    const float* bias  = (const float*)d_in[7];
    const float* taus  = (const float*)d_in[8];
    float* out = (float*)d_out;

    const int main_smem = SMEM_U32 * 4;   // 106496 B -> 2 blocks/SM
    cudaFuncSetAttribute(main_kernel, cudaFuncAttributeMaxDynamicSharedMemorySize, main_smem);

    pack_all_kernel<<<2432, 256>>>(win, wout, r0, w_);
    base_gemm_kernel<<<256, 256>>>();
    base_reduce_kernel<<<256, 256>>>(r0, taus);
    main_kernel<<<T_STEPS, 256, main_smem>>>(u, noise, bias, out);
}

// round 7
// speedup vs baseline: 2.9469x; 1.2786x over previous
#include <cuda_runtime.h>
#include <cuda_fp16.h>
#include <cstdint>
#include <cstddef>

#define T_STEPS 512
#define DH      2048
#define DI      64
#define DO      64
#define BATCH   128
#define HC      64
#define NCHUNK  (DH / HC)        // 32
#define NB      64               // batch cols per block
#define USTR    72               // u32 stride (conflict-free: 72 mod 32 = 8)

// ---- device scratch ----
__device__ float    g_base[DH * BATCH];            // 1 MB
__device__ float    g_part[4 * DH * BATCH];        // 4 MB K-quarter partials
__device__ unsigned g_win_h[NCHUNK * 2048];        // fp16x2 win A-fragments
__device__ unsigned g_wout_h[NCHUNK * 2048];       // fp16x2 wout A-fragments (K-permuted)
__device__ unsigned g_wfrag[4 * 32 * 32 * 4 * 32 * 4]; // |w| fp16 A-frags, 8 MB
__device__ unsigned g_spk[1024 * 128];             // sigmoid(r0) fp16 k-pair

// ---------- helpers ----------
__device__ __forceinline__ float sigm_exact(float x) {
    return __fdividef(1.0f, 1.0f + __expf(-x));
}
__device__ __forceinline__ float sigm(float x) {
    float t;
    asm("tanh.approx.f32 %0, %1;" : "=f"(t) : "f"(0.5f * x));
    return fmaf(0.5f, t, 0.5f);
}
__device__ __forceinline__ unsigned packh2(float a, float b) {
    __half2 h = __floats2half2_rn(a, b);   // a -> low half
    return *(unsigned*)&h;
}
__device__ __forceinline__ void mma_f16(float& c0, float& c1, float& c2, float& c3,
                                        unsigned a0, unsigned a1, unsigned a2, unsigned a3,
                                        unsigned b0, unsigned b1) {
    asm volatile("mma.sync.aligned.m16n8k16.row.col.f32.f16.f16.f32 "
                 "{%0,%1,%2,%3}, {%4,%5,%6,%7}, {%8,%9}, {%0,%1,%2,%3};"
                 : "+f"(c0), "+f"(c1), "+f"(c2), "+f"(c3)
                 : "r"(a0), "r"(a1), "r"(a2), "r"(a3), "r"(b0), "r"(b1));
}

// ---------- kernel 1: all packing (win, wout, |w|, sigmoid(r0)) ----------
__global__ void pack_all_kernel(const float* __restrict__ win,
                                const float* __restrict__ wout,
                                const float* __restrict__ r0,
                                const float* __restrict__ w_) {
    int bx = blockIdx.x;
    int tid = threadIdx.x;
    if (bx < 128) {
        int tg = (bx & 63) * 256 + tid;       // 0..16383
        int lane = tg & 31;
        int mt = (tg >> 5) & 3;
        int kt = (tg >> 7) & 3;
        int c  = tg >> 9;
        uint4 oh;
        if (bx < 64) {
            // win: natural K order
            int r = (c * 4 + mt) * 16 + (lane >> 2);
            int k0 = kt * 16 + 2 * (lane & 3);
            oh.x = packh2(win[r * DI + k0],           win[r * DI + k0 + 1]);
            oh.y = packh2(win[(r + 8) * DI + k0],     win[(r + 8) * DI + k0 + 1]);
            oh.z = packh2(win[r * DI + k0 + 8],       win[r * DI + k0 + 9]);
            oh.w = packh2(win[(r + 8) * DI + k0 + 8], win[(r + 8) * DI + k0 + 9]);
            *(uint4*)(g_win_h + (size_t)tg * 4) = oh;
        } else {
            // wout: permuted K so that pair (2p,2p+1) <-> h = (Hp, Hp+8)
            // k = kt*16 + 2*q3 -> h0 = kt*16 + q3;  k+8 -> h2 = kt*16 + 4 + q3
            int r = mt * 16 + (lane >> 2);
            int q3 = lane & 3;
            int h0 = c * HC + kt * 16 + q3;       // pair low  (e=0), high = h0+8
            int h2 = h0 + 4;                      // k+8 pair
            oh.x = packh2(wout[r * DH + h0],           wout[r * DH + h0 + 8]);
            oh.y = packh2(wout[(r + 8) * DH + h0],     wout[(r + 8) * DH + h0 + 8]);
            oh.z = packh2(wout[r * DH + h2],           wout[r * DH + h2 + 8]);
            oh.w = packh2(wout[(r + 8) * DH + h2],     wout[(r + 8) * DH + h2 + 8]);
            *(uint4*)(g_wout_h + (size_t)tg * 4) = oh;
        }
    } else if (bx < 384) {
        int i = (bx - 128) * 256 + tid;       // 0..65535
        int bp = i & 63;
        int kp = i >> 6;                       // 0..1023
        float2 ra = *(const float2*)(r0 + (size_t)(2 * kp) * BATCH + 2 * bp);
        float2 rb = *(const float2*)(r0 + (size_t)(2 * kp + 1) * BATCH + 2 * bp);
        uint2 o;
        o.x = packh2(sigm_exact(ra.x), sigm_exact(rb.x));
        o.y = packh2(sigm_exact(ra.y), sigm_exact(rb.y));
        *(uint2*)(g_spk + (size_t)kp * BATCH + 2 * bp) = o;
    } else {
        int tg = (bx - 384) * 256 + tid;      // 0..524287
        int lane = tg & 31;
        int mt = (tg >> 5) & 3;
        int kt = (tg >> 7) & 31;
        int hc = (tg >> 12) & 31;
        int kq = tg >> 17;
        int r  = hc * HC + mt * 16 + (lane >> 2);
        int k0 = kq * 512 + kt * 16 + 2 * (lane & 3);
        uint4 oh;
        oh.x = packh2(fabsf(w_[(size_t)r * DH + k0]),
                      fabsf(w_[(size_t)r * DH + k0 + 1]));
        oh.y = packh2(fabsf(w_[(size_t)(r + 8) * DH + k0]),
                      fabsf(w_[(size_t)(r + 8) * DH + k0 + 1]));
        oh.z = packh2(fabsf(w_[(size_t)r * DH + k0 + 8]),
                      fabsf(w_[(size_t)r * DH + k0 + 9]));
        oh.w = packh2(fabsf(w_[(size_t)(r + 8) * DH + k0 + 8]),
                      fabsf(w_[(size_t)(r + 8) * DH + k0 + 9]));
        *(uint4*)(g_wfrag + (size_t)tg * 4) = oh;
    }
}

// ---------- kernel 2: base GEMM partials ----------
__global__ void __launch_bounds__(256)
base_gemm_kernel() {
    int bx = blockIdx.x;
    int kq = bx >> 6;
    int hc = (bx >> 1) & 31;
    int nh = bx & 1;

    int tid  = threadIdx.x;
    int lane = tid & 31;
    int w    = tid >> 5;
    int qq   = lane & 3;
    int rr   = lane >> 2;
    int n    = nh * NB + w * 8 + rr;

    float C[4][4];
#pragma unroll
    for (int a = 0; a < 4; ++a)
#pragma unroll
        for (int q = 0; q < 4; ++q) C[a][q] = 0.0f;

    const uint4* Af = ((const uint4*)g_wfrag) + ((size_t)(kq * 32 + hc) * 32) * 128;

#pragma unroll 4
    for (int kt = 0; kt < 32; ++kt) {
        int kp = kq * 256 + kt * 8;
        unsigned b0 = g_spk[(size_t)(kp + qq) * BATCH + n];
        unsigned b1 = g_spk[(size_t)(kp + 4 + qq) * BATCH + n];
#pragma unroll
        for (int mt = 0; mt < 4; ++mt) {
            uint4 a4 = Af[(kt * 4 + mt) * 32 + lane];
            mma_f16(C[mt][0], C[mt][1], C[mt][2], C[mt][3],
                    a4.x, a4.y, a4.z, a4.w, b0, b1);
        }
    }

    float* dst = g_part + (size_t)kq * DH * BATCH;
    int n0 = nh * NB + w * 8 + 2 * qq;
#pragma unroll
    for (int mt = 0; mt < 4; ++mt)
#pragma unroll
        for (int hh = 0; hh < 2; ++hh) {
            int h = hc * HC + mt * 16 + hh * 8 + rr;
            *(float2*)(dst + (size_t)h * BATCH + n0) =
                make_float2(C[mt][hh * 2], C[mt][hh * 2 + 1]);
        }
}

// ---------- kernel 3: base = (1-a)*r0 + a*(p0+p1+p2+p3) ----------
__global__ void base_reduce_kernel(const float* __restrict__ r0,
                                   const float* __restrict__ taus) {
    int i4 = (blockIdx.x * blockDim.x + threadIdx.x) * 4;
    int h  = i4 >> 7;
    float alpha = 1.0f / taus[h];
    float om = 1.0f - alpha;
    float4 rv = *(const float4*)(r0 + i4);
    float4 p0 = *(const float4*)(g_part + i4);
    float4 p1 = *(const float4*)(g_part + DH * BATCH + i4);
    float4 p2 = *(const float4*)(g_part + 2 * DH * BATCH + i4);
    float4 p3 = *(const float4*)(g_part + 3 * DH * BATCH + i4);
    float4 o;
    o.x = om * rv.x + alpha * (p0.x + p1.x + p2.x + p3.x);
    o.y = om * rv.y + alpha * (p0.y + p1.y + p2.y + p3.y);
    o.z = om * rv.z + alpha * (p0.z + p1.z + p2.z + p3.z);
    o.w = om * rv.w + alpha * (p0.w + p1.w + p2.w + p3.w);
    *(float4*)(g_base + i4) = o;
}

// ---------- kernel 4: main, 2 timesteps per block ----------
// smem (u32): WINB[2] 0..4096 | WOUTB[2] 4096..8192 |
//   UH0 8192..10496 | UH1 10496..12800 |
//   S0[2] 12800..17408 | S1[2] 17408..22016   (2304 each, stride 72, 32 rows)
#define OFF_WOUT 4096
#define OFF_UH0  8192
#define OFF_UH1  10496
#define OFF_S0   12800
#define OFF_S1   17408
#define SMEM_U32 22016

__global__ void __launch_bounds__(256, 2)
main_kernel(const float* __restrict__ u,
            const float* __restrict__ noise,
            const float* __restrict__ bias,
            float* __restrict__ out) {
    extern __shared__ unsigned smu[];
    unsigned* WINB  = smu;
    unsigned* WOUTB = smu + OFF_WOUT;

    int tid  = threadIdx.x;
    int lane = tid & 31;
    int w    = tid >> 5;
    int qq   = lane & 3;
    int rr   = lane >> 2;

    int t0 = (blockIdx.x >> 1) * 2;
    int t1 = t0 + 1;
    int nb = (blockIdx.x & 1) * NB;

    float* xsout = out + (size_t)T_STEPS * DO * BATCH;

    // ---- prologue: stage u[t0], u[t1] (fp16 hi only, k-pair interleave) ----
#pragma unroll
    for (int tt = 0; tt < 2; ++tt) {
        const float* ut = u + (size_t)(t0 + tt) * DI * BATCH + nb;
        unsigned* uh = smu + (tt ? OFF_UH1 : OFF_UH0);
#pragma unroll
        for (int i = 0; i < 4; ++i) {
            int idx = tid + i * 256;
            int dp  = idx >> 5;
            int b2  = (idx & 31) * 2;
            float2 ra = *(const float2*)(ut + (2 * dp) * BATCH + b2);
            float2 rb = *(const float2*)(ut + (2 * dp + 1) * BATCH + b2);
            *(uint2*)(uh + dp * USTR + b2) =
                make_uint2(packh2(ra.x, rb.x), packh2(ra.y, rb.y));
        }
    }
    ((uint4*)WINB)[tid]        = ((const uint4*)g_win_h)[tid];
    ((uint4*)WINB)[tid + 256]  = ((const uint4*)g_win_h)[tid + 256];
    ((uint4*)WOUTB)[tid]       = ((const uint4*)g_wout_h)[tid];
    ((uint4*)WOUTB)[tid + 256] = ((const uint4*)g_wout_h)[tid + 256];

    float C2a[4][4], C2b[4][4];
#pragma unroll
    for (int a = 0; a < 4; ++a)
#pragma unroll
        for (int q = 0; q < 4; ++q) { C2a[a][q] = 0.0f; C2b[a][q] = 0.0f; }

    int n0 = nb + w * 8 + 2 * qq;
    int nl = w * 8 + 2 * qq;
    int n  = w * 8 + rr;

    __syncthreads();

    for (int c = 0; c < NCHUNK; ++c) {
        // ---- prefetch base (shared by t0/t1) + noise[t0] ----
        float2 bs[8], nz[8];
#pragma unroll
        for (int mt = 0; mt < 4; ++mt)
#pragma unroll
            for (int hh = 0; hh < 2; ++hh) {
                int hg = c * HC + mt * 16 + hh * 8 + rr;
                bs[mt * 2 + hh] = *(const float2*)(g_base + (size_t)hg * BATCH + n0);
                nz[mt * 2 + hh] = *(const float2*)(noise + ((size_t)t0 * DH + hg) * BATCH + n0);
            }

        // ---- stage win[c+1] ----
        if (c + 1 < NCHUNK) {
            uint4* dst = (uint4*)(WINB + ((c + 1) & 1) * 2048);
            const uint4* src = ((const uint4*)g_win_h) + (size_t)(c + 1) * 512;
            dst[tid]       = src[tid];
            dst[tid + 256] = src[tid + 256];
        }

        // ---- GEMM1 both t: inp = win_h @ u_h (single pass) ----
        const unsigned* A1 = WINB + (c & 1) * 2048;
        const unsigned* uh0 = smu + OFF_UH0;
        const unsigned* uh1 = smu + OFF_UH1;
        float C1a[4][4], C1b[4][4];
#pragma unroll
        for (int a = 0; a < 4; ++a)
#pragma unroll
            for (int q = 0; q < 4; ++q) { C1a[a][q] = 0.0f; C1b[a][q] = 0.0f; }

#pragma unroll
        for (int kt = 0; kt < 4; ++kt) {
            int ra = (kt * 8 + qq) * USTR + n;
            int rb = (kt * 8 + 4 + qq) * USTR + n;
            unsigned ah0 = uh0[ra], ah1 = uh0[rb];
            unsigned bh0 = uh1[ra], bh1 = uh1[rb];
#pragma unroll
            for (int mt = 0; mt < 4; ++mt) {
                uint4 a4 = *(const uint4*)(A1 + ((kt * 4 + mt) * 32 + lane) * 4);
                mma_f16(C1a[mt][0], C1a[mt][1], C1a[mt][2], C1a[mt][3],
                        a4.x, a4.y, a4.z, a4.w, ah0, ah1);
                mma_f16(C1b[mt][0], C1b[mt][1], C1b[mt][2], C1b[mt][3],
                        a4.x, a4.y, a4.z, a4.w, bh0, bh1);
            }
        }

        // ---- epilogue t0: xs out + S (permuted pair layout, STS.64) ----
        unsigned* S0 = smu + OFF_S0 + (c & 1) * 2304;
#pragma unroll
        for (int mt = 0; mt < 4; ++mt) {
            int hg0 = c * HC + mt * 16 + rr;
            float2 nn0 = nz[mt * 2], nn1 = nz[mt * 2 + 1];
            float2 bb0 = bs[mt * 2], bb1 = bs[mt * 2 + 1];
            float xa0 = C1a[mt][0] + nn0.x + bb0.x;   // hh0 col0
            float xa1 = C1a[mt][1] + nn0.y + bb0.y;   // hh0 col1
            float xb0 = C1a[mt][2] + nn1.x + bb1.x;   // hh1 col0
            float xb1 = C1a[mt][3] + nn1.y + bb1.y;   // hh1 col1
            *(float2*)(xsout + ((size_t)t0 * DH + hg0) * BATCH + n0) = make_float2(xa0, xa1);
            *(float2*)(xsout + ((size_t)t0 * DH + hg0 + 8) * BATCH + n0) = make_float2(xb0, xb1);
            uint2 sw;
            sw.x = packh2(sigm(xa0), sigm(xb0));
            sw.y = packh2(sigm(xa1), sigm(xb1));
            *(uint2*)(S0 + (mt * 8 + rr) * USTR + nl) = sw;
        }

        // ---- prefetch noise[t1], epilogue t1 ----
#pragma unroll
        for (int mt = 0; mt < 4; ++mt)
#pragma unroll
            for (int hh = 0; hh < 2; ++hh) {
                int hg = c * HC + mt * 16 + hh * 8 + rr;
                nz[mt * 2 + hh] = *(const float2*)(noise + ((size_t)t1 * DH + hg) * BATCH + n0);
            }
        unsigned* S1 = smu + OFF_S1 + (c & 1) * 2304;
#pragma unroll
        for (int mt = 0; mt < 4; ++mt) {
            int hg0 = c * HC + mt * 16 + rr;
            float2 nn0 = nz[mt * 2], nn1 = nz[mt * 2 + 1];
            float2 bb0 = bs[mt * 2], bb1 = bs[mt * 2 + 1];
            float xa0 = C1b[mt][0] + nn0.x + bb0.x;
            float xa1 = C1b[mt][1] + nn0.y + bb0.y;
            float xb0 = C1b[mt][2] + nn1.x + bb1.x;
            float xb1 = C1b[mt][3] + nn1.y + bb1.y;
            *(float2*)(xsout + ((size_t)t1 * DH + hg0) * BATCH + n0) = make_float2(xa0, xa1);
            *(float2*)(xsout + ((size_t)t1 * DH + hg0 + 8) * BATCH + n0) = make_float2(xb0, xb1);
            uint2 sw;
            sw.x = packh2(sigm(xa0), sigm(xb0));
            sw.y = packh2(sigm(xa1), sigm(xb1));
            *(uint2*)(S1 + (mt * 8 + rr) * USTR + nl) = sw;
        }
        __syncthreads();   // the one sync per chunk

        // ---- stage wout[c+1] ----
        if (c + 1 < NCHUNK) {
            uint4* dst = (uint4*)(WOUTB + ((c + 1) & 1) * 2048);
            const uint4* src = ((const uint4*)g_wout_h) + (size_t)(c + 1) * 512;
            dst[tid]       = src[tid];
            dst[tid + 256] = src[tid + 256];
        }

        // ---- GEMM2 both t: out += wout_h @ s (permuted K) ----
        const unsigned* A2  = WOUTB + (c & 1) * 2048;
        const unsigned* S0r = smu + OFF_S0 + (c & 1) * 2304;
        const unsigned* S1r = smu + OFF_S1 + (c & 1) * 2304;
#pragma unroll
        for (int kt = 0; kt < 4; ++kt) {
            int ra = (kt * 8 + qq) * USTR + n;
            int rb = (kt * 8 + 4 + qq) * USTR + n;
            unsigned sa0 = S0r[ra], sa1 = S0r[rb];
            unsigned sb0 = S1r[ra], sb1 = S1r[rb];
#pragma unroll
            for (int mt = 0; mt < 4; ++mt) {
                uint4 a4 = *(const uint4*)(A2 + ((kt * 4 + mt) * 32 + lane) * 4);
                mma_f16(C2a[mt][0], C2a[mt][1], C2a[mt][2], C2a[mt][3],
                        a4.x, a4.y, a4.z, a4.w, sa0, sa1);
                mma_f16(C2b[mt][0], C2b[mt][1], C2b[mt][2], C2b[mt][3],
                        a4.x, a4.y, a4.z, a4.w, sb0, sb1);
            }
        }
    }

    // ---- write outputs[t0], outputs[t1] ----
#pragma unroll
    for (int mt = 0; mt < 4; ++mt) {
        int o0 = mt * 16 + rr;
        float bv0 = __ldg(bias + o0);
        float bv8 = __ldg(bias + o0 + 8);
        *(float2*)(out + ((size_t)t0 * DO + o0) * BATCH + n0) =
            make_float2(C2a[mt][0] + bv0, C2a[mt][1] + bv0);
        *(float2*)(out + ((size_t)t0 * DO + o0 + 8) * BATCH + n0) =
            make_float2(C2a[mt][2] + bv8, C2a[mt][3] + bv8);
        *(float2*)(out + ((size_t)t1 * DO + o0) * BATCH + n0) =
            make_float2(C2b[mt][0] + bv0, C2b[mt][1] + bv0);
        *(float2*)(out + ((size_t)t1 * DO + o0 + 8) * BATCH + n0) =
            make_float2(C2b[mt][2] + bv8, C2b[mt][3] + bv8);
    }
}

extern "C" void kernel_launch(void* const* d_in, const int* in_sizes, int n_in,
                              void* d_out, int out_size) {
    const float* u     = (const float*)d_in[0];
    const float* r0    = (const float*)d_in[1];
    const float* noise = (const float*)d_in[2];
    const float* win   = (const float*)d_in[3];
    const float* w_    = (const float*)d_in[4];
    // d_in[5] = m_diag: unused — |_w * (+-1)| == |_w|
    const float* wout  = (const float*)d_in[6];
    const float* bias  = (const float*)d_in[7];
    const float* taus  = (const float*)d_in[8];
    float* out = (float*)d_out;

    const int main_smem = SMEM_U32 * 4;   // 88064 B -> 2 blocks/SM
    cudaFuncSetAttribute(main_kernel, cudaFuncAttributeMaxDynamicSharedMemorySize, main_smem);

    pack_all_kernel<<<2432, 256>>>(win, wout, r0, w_);
    base_gemm_kernel<<<256, 256>>>();
    base_reduce_kernel<<<256, 256>>>(r0, taus);
    main_kernel<<<T_STEPS, 256, main_smem>>>(u, noise, bias, out);
}